// round 16
// baseline (speedup 1.0000x reference)
#include <cuda_runtime.h>

#define BB 2
#define NN 512
#define DD 512
#define HH 8
#define EE 128
#define MSPLIT 4
#define MCH (NN / MSPLIT)   // 128 m per block
#define PR 4                // bn rows per a_kernel block

// Scratch (no cudaMalloc allowed)
__device__ float g_o12[BB * NN * 16];             // o1 | o2 per row
__device__ float g_A [(size_t)BB * NN * EE * HH]; // 1M floats = 4 MB

// ---------------------------------------------------------------------------
// Kernel 1: o12 = x @ W12^T + b12.  ONE bn row per block (grid 1024 -> high
// MLP to hide DRAM latency). 4 warps x 4 h-dots each (ILP).
// ---------------------------------------------------------------------------
__global__ void __launch_bounds__(128) o12_kernel(
    const float* __restrict__ x,    // (B,N,D)
    const float* __restrict__ W12,  // (16,D)
    const float* __restrict__ b12)  // (16,)
{
    const int bn   = blockIdx.x;
    const int tid  = threadIdx.x;       // 128 threads = 4 warps
    const int warp = tid >> 5;          // 0..3 -> h-group warp*4..warp*4+3
    const int lane = tid & 31;

    __shared__ float xs[DD];            // 2 KB

    reinterpret_cast<float4*>(xs)[tid] =
        __ldg(reinterpret_cast<const float4*>(x + (size_t)bn * DD) + tid);
    __syncthreads();

    float a0 = 0.f, a1 = 0.f, a2 = 0.f, a3 = 0.f;
    const float* w = W12 + (warp * 4) * DD;
    #pragma unroll 4
    for (int i = lane; i < DD; i += 32) {
        const float xv = xs[i];
        a0 += xv * __ldg(w + 0 * DD + i);
        a1 += xv * __ldg(w + 1 * DD + i);
        a2 += xv * __ldg(w + 2 * DD + i);
        a3 += xv * __ldg(w + 3 * DD + i);
    }
    #pragma unroll
    for (int o = 16; o; o >>= 1) {
        a0 += __shfl_xor_sync(0xffffffffu, a0, o);
        a1 += __shfl_xor_sync(0xffffffffu, a1, o);
        a2 += __shfl_xor_sync(0xffffffffu, a2, o);
        a3 += __shfl_xor_sync(0xffffffffu, a3, o);
    }
    if (lane == 0) {
        const int h = warp * 4;
        g_o12[bn * 16 + h + 0] = a0 + __ldg(b12 + h + 0);
        g_o12[bn * 16 + h + 1] = a1 + __ldg(b12 + h + 1);
        g_o12[bn * 16 + h + 2] = a2 + __ldg(b12 + h + 2);
        g_o12[bn * 16 + h + 3] = a3 + __ldg(b12 + h + 3);
    }
}

// ---------------------------------------------------------------------------
// Kernel 2: A[bn, e, j] = sum_i o1[bn, i] * W3[e, i*8+j].
// Block handles PR=4 bn rows: stage W3 once (padded pitch 65 -> conflict-free
// column reads), then thread (r = tid>>7, e = tid&127) does 64 FMA.
// ---------------------------------------------------------------------------
__global__ void __launch_bounds__(512) a_kernel(
    const float* __restrict__ W3)   // (E,64)
{
    const int bn0  = blockIdx.x * PR;
    const int tid  = threadIdx.x;       // 512 threads

    __shared__ float w3s[EE * 65];      // 33 KB

    for (int idx = tid; idx < EE * 64; idx += 512) {
        int e = idx >> 6, k = idx & 63;
        w3s[e * 65 + k] = W3[idx];
    }
    __syncthreads();

    const int r = tid >> 7;             // 0..3
    const int e = tid & 127;

    float o1r[HH];
    {
        const float* o1 = g_o12 + (size_t)(bn0 + r) * 16;
        #pragma unroll
        for (int i = 0; i < HH; i++) o1r[i] = __ldg(o1 + i);   // L1 broadcast
    }

    const float* w3 = w3s + e * 65;     // bank=(e+c)%32: conflict-free
    float a[HH];
    #pragma unroll
    for (int j = 0; j < HH; j++) a[j] = 0.f;
    #pragma unroll
    for (int i = 0; i < HH; i++) {
        #pragma unroll
        for (int j = 0; j < HH; j++)
            a[j] += o1r[i] * w3[i * HH + j];
    }
    float* Ao = g_A + ((size_t)(bn0 + r) * EE + e) * HH;
    reinterpret_cast<float4*>(Ao)[0] = make_float4(a[0], a[1], a[2], a[3]);
    reinterpret_cast<float4*>(Ao)[1] = make_float4(a[4], a[5], a[6], a[7]);
}

// ---------------------------------------------------------------------------
// Kernel 3 (R8's proven loop): block per (bn, m-chunk).
// out[bn,m,e] = b3[e] + sum_j A[bn,e,j]*o2[b,m,j]
// e-PAIR per lane (16 A regs); warp-pairs split the e-range; scalar FFMA;
// coalesced 256B streaming STG.64 per warp per m. 40 regs -> 75% occ cap.
// ---------------------------------------------------------------------------
__global__ void __launch_bounds__(256, 6) main_kernel(
    const float* __restrict__ b3,   // (E,)
    float* __restrict__ out)        // (B,N,N,E)
{
    const int bn   = blockIdx.x;
    const int b    = bn >> 9;
    const int mc   = blockIdx.y;
    const int tid  = threadIdx.x;      // 256 = 8 warps
    const int warp = tid >> 5;
    const int lane = tid & 31;

    __shared__ float o2s[MCH * HH];    // 4 KB

    // o2 slice from g_o12 (upper 8 floats of each 16-float row)
    for (int i = tid; i < MCH * 2; i += 256) {
        const int row = i >> 1, h = i & 1;
        reinterpret_cast<float4*>(o2s)[row * 2 + h] =
            __ldg(reinterpret_cast<const float4*>(
                g_o12 + ((size_t)(b * NN) + mc * MCH + row) * 16 + 8 + h * 4));
    }

    // lane's e-pair: e = 64*(warp&1) + 2*lane  -> 16 A regs
    const int ebase = ((warp & 1) << 6) + (lane << 1);
    float a0[HH], a1[HH];
    {
        const float4* Ab = reinterpret_cast<const float4*>(
            g_A + ((size_t)bn * EE + ebase) * HH);
        float4 v0 = Ab[0], v1 = Ab[1], v2 = Ab[2], v3 = Ab[3];
        a0[0]=v0.x; a0[1]=v0.y; a0[2]=v0.z; a0[3]=v0.w;
        a0[4]=v1.x; a0[5]=v1.y; a0[6]=v1.z; a0[7]=v1.w;
        a1[0]=v2.x; a1[1]=v2.y; a1[2]=v2.z; a1[3]=v2.w;
        a1[4]=v3.x; a1[5]=v3.y; a1[6]=v3.z; a1[7]=v3.w;
    }
    const float2 bv = reinterpret_cast<const float2*>(b3)[ebase >> 1];

    __syncthreads();

    // out as float2: row (bn,m) has EE/2 = 64 float2; lane owns slot ebase/2
    float2* outp = reinterpret_cast<float2*>(out)
                 + ((size_t)bn * NN + (size_t)mc * MCH) * (EE / 2) + (ebase >> 1);

    for (int m = (warp >> 1); m < MCH; m += 4) {
        const float4 p  = reinterpret_cast<const float4*>(o2s + m * HH)[0];
        const float4 qv = reinterpret_cast<const float4*>(o2s + m * HH)[1];
        const float o2r[HH] = {p.x, p.y, p.z, p.w, qv.x, qv.y, qv.z, qv.w};

        float ax = bv.x, ay = bv.y;
        #pragma unroll
        for (int j = 0; j < HH; j++) {
            ax += a0[j] * o2r[j];
            ay += a1[j] * o2r[j];
        }
        __stcs(outp + (size_t)m * (EE / 2), make_float2(ax, ay));
    }
}

extern "C" void kernel_launch(void* const* d_in, const int* in_sizes, int n_in,
                              void* d_out, int out_size)
{
    const float* x   = (const float*)d_in[0];
    const float* W12 = (const float*)d_in[1];
    const float* b12 = (const float*)d_in[2];
    const float* W3  = (const float*)d_in[3];
    const float* b3  = (const float*)d_in[4];
    float* out = (float*)d_out;

    o12_kernel<<<BB * NN, 128>>>(x, W12, b12);
    a_kernel  <<<BB * NN / PR, 512>>>(W3);
    main_kernel<<<dim3(BB * NN, MSPLIT), 256>>>(b3, out);
}

// round 17
// speedup vs baseline: 1.0385x; 1.0385x over previous
#include <cuda_runtime.h>

#define BB 2
#define NN 512
#define DD 512
#define HH 8
#define EE 128
#define MSPLIT 2
#define MCH (NN / MSPLIT)   // 256 m per block
#define PR 4                // bn rows per prep block

// Scratch (no cudaMalloc allowed)
__device__ float g_o2[BB * NN * HH];              // 8K floats
__device__ float g_A [(size_t)BB * NN * EE * HH]; // 1M floats = 4 MB

__device__ __forceinline__ void cp_async4(unsigned saddr, const void* gptr) {
    asm volatile("cp.async.ca.shared.global [%0], [%1], 4;" :: "r"(saddr), "l"(gptr));
}
__device__ __forceinline__ void cp_async16(unsigned saddr, const void* gptr) {
    asm volatile("cp.async.ca.shared.global [%0], [%1], 16;" :: "r"(saddr), "l"(gptr));
}

// ---------------------------------------------------------------------------
// Kernel 1: per PR=4 bn rows: o12 = x@W12^T + b12 ; o2 -> scratch ;
// A[e][j] = sum_i o1[i]*W3[e,i*8+j].
// Latency surgery vs R10: W12 -> registers BEFORE the staging barrier;
// x + W3 staged via cp.async (no LDG->STS register dependency).
// Static smem: 33280 (w3s) + 8192 (xs) + 128 (o1s) = 41.6 KB < 48 KB.
// ---------------------------------------------------------------------------
__global__ void __launch_bounds__(512) prep_kernel(
    const float* __restrict__ x,    // (B,N,D)
    const float* __restrict__ W12,  // (16,D)
    const float* __restrict__ b12,  // (16,)
    const float* __restrict__ W3)   // (E,64)
{
    const int bn0  = blockIdx.x * PR;
    const int tid  = threadIdx.x;       // 512 threads = 16 warps
    const int warp = tid >> 5;          // = h index in phase A
    const int lane = tid & 31;

    __shared__ __align__(16) float w3s[EE * 65]; // pitch 65 -> conflict-free cols
    __shared__ __align__(16) float xs[PR * DD];
    __shared__ float o1s[PR][HH];

    // W12 row for this warp's h -> registers (latency hidden behind staging)
    float wreg[16];
    {
        const float* w = W12 + warp * DD + lane;
        #pragma unroll
        for (int k = 0; k < 16; k++) wreg[k] = __ldg(w + 32 * k);
    }

    // cp.async staging: x rows (16B ops) + W3 padded (4B ops)
    {
        unsigned xsa = (unsigned)__cvta_generic_to_shared(xs);
        const float4* xg = reinterpret_cast<const float4*>(x + (size_t)bn0 * DD);
        #pragma unroll
        for (int i = tid; i < PR * DD / 4; i += 512)
            cp_async16(xsa + i * 16, xg + i);

        unsigned wsa = (unsigned)__cvta_generic_to_shared(w3s);
        #pragma unroll
        for (int idx = tid; idx < EE * 64; idx += 512) {
            int e = idx >> 6, k = idx & 63;
            cp_async4(wsa + (e * 65 + k) * 4, W3 + idx);
        }
        asm volatile("cp.async.commit_group;" ::: "memory");
        asm volatile("cp.async.wait_group 0;" ::: "memory");
    }
    __syncthreads();

    // Phase A: warp h, 4 rows at once, W12 from registers
    {
        float a0 = 0.f, a1 = 0.f, a2 = 0.f, a3 = 0.f;
        #pragma unroll
        for (int k = 0; k < 16; k++) {
            const int i = lane + 32 * k;
            const float wv = wreg[k];
            a0 += wv * xs[0 * DD + i];
            a1 += wv * xs[1 * DD + i];
            a2 += wv * xs[2 * DD + i];
            a3 += wv * xs[3 * DD + i];
        }
        #pragma unroll
        for (int o = 16; o; o >>= 1) {
            a0 += __shfl_xor_sync(0xffffffffu, a0, o);
            a1 += __shfl_xor_sync(0xffffffffu, a1, o);
            a2 += __shfl_xor_sync(0xffffffffu, a2, o);
            a3 += __shfl_xor_sync(0xffffffffu, a3, o);
        }
        if (lane == 0) {
            const float bb = __ldg(b12 + warp);
            float v[PR] = {a0 + bb, a1 + bb, a2 + bb, a3 + bb};
            #pragma unroll
            for (int r = 0; r < PR; r++) {
                if (warp < HH) o1s[r][warp] = v[r];
                else           g_o2[(bn0 + r) * HH + (warp - HH)] = v[r];
            }
        }
    }
    __syncthreads();

    // Phase B: r = tid/128, e = tid%128.
    {
        const int r = tid >> 7;
        const int e = tid & 127;

        float o1r[HH];
        #pragma unroll
        for (int i = 0; i < HH; i++) o1r[i] = o1s[r][i];   // smem broadcast

        const float* w3 = w3s + e * 65;     // bank=(e+c)%32: conflict-free
        float a[HH];
        #pragma unroll
        for (int j = 0; j < HH; j++) a[j] = 0.f;
        #pragma unroll
        for (int i = 0; i < HH; i++) {
            #pragma unroll
            for (int j = 0; j < HH; j++)
                a[j] += o1r[i] * w3[i * HH + j];
        }
        float* Ao = g_A + ((size_t)(bn0 + r) * EE + e) * HH;
        reinterpret_cast<float4*>(Ao)[0] = make_float4(a[0], a[1], a[2], a[3]);
        reinterpret_cast<float4*>(Ao)[1] = make_float4(a[4], a[5], a[6], a[7]);
    }
}

// ---------------------------------------------------------------------------
// Kernel 2 (R8/R10 proven loop, MSPLIT=2): block per (bn, m-half).
// out[bn,m,e] = b3[e] + sum_j A[bn,e,j]*o2[b,m,j]
// e-PAIR per lane (16 A regs); warp-pairs split the e-range; scalar FFMA;
// coalesced 256B streaming STG.64 per warp per m. 40 regs -> 75% occ cap.
// ---------------------------------------------------------------------------
__global__ void __launch_bounds__(256, 6) main_kernel(
    const float* __restrict__ b3,   // (E,)
    float* __restrict__ out)        // (B,N,N,E)
{
    const int bn   = blockIdx.x;
    const int b    = bn >> 9;
    const int mc   = blockIdx.y;
    const int tid  = threadIdx.x;      // 256 = 8 warps
    const int warp = tid >> 5;
    const int lane = tid & 31;

    __shared__ float o2s[MCH * HH];    // 8 KB

    const float4* o2g = reinterpret_cast<const float4*>(
        g_o2 + ((size_t)b * NN + (size_t)mc * MCH) * HH);
    for (int i = tid; i < MCH * HH / 4; i += 256)
        reinterpret_cast<float4*>(o2s)[i] = __ldg(o2g + i);

    // lane's e-pair: e = 64*(warp&1) + 2*lane  -> 16 A regs
    const int ebase = ((warp & 1) << 6) + (lane << 1);
    float a0[HH], a1[HH];
    {
        const float4* Ab = reinterpret_cast<const float4*>(
            g_A + ((size_t)bn * EE + ebase) * HH);
        float4 v0 = Ab[0], v1 = Ab[1], v2 = Ab[2], v3 = Ab[3];
        a0[0]=v0.x; a0[1]=v0.y; a0[2]=v0.z; a0[3]=v0.w;
        a0[4]=v1.x; a0[5]=v1.y; a0[6]=v1.z; a0[7]=v1.w;
        a1[0]=v2.x; a1[1]=v2.y; a1[2]=v2.z; a1[3]=v2.w;
        a1[4]=v3.x; a1[5]=v3.y; a1[6]=v3.z; a1[7]=v3.w;
    }
    const float2 bv = reinterpret_cast<const float2*>(b3)[ebase >> 1];

    __syncthreads();

    // out as float2: row (bn,m) has EE/2 = 64 float2; lane owns slot ebase/2
    float2* outp = reinterpret_cast<float2*>(out)
                 + ((size_t)bn * NN + (size_t)mc * MCH) * (EE / 2) + (ebase >> 1);

    for (int m = (warp >> 1); m < MCH; m += 4) {
        const float4 p  = reinterpret_cast<const float4*>(o2s + m * HH)[0];
        const float4 qv = reinterpret_cast<const float4*>(o2s + m * HH)[1];
        const float o2r[HH] = {p.x, p.y, p.z, p.w, qv.x, qv.y, qv.z, qv.w};

        float ax = bv.x, ay = bv.y;
        #pragma unroll
        for (int j = 0; j < HH; j++) {
            ax += a0[j] * o2r[j];
            ay += a1[j] * o2r[j];
        }
        __stcs(outp + (size_t)m * (EE / 2), make_float2(ax, ay));
    }
}

extern "C" void kernel_launch(void* const* d_in, const int* in_sizes, int n_in,
                              void* d_out, int out_size)
{
    const float* x   = (const float*)d_in[0];
    const float* W12 = (const float*)d_in[1];
    const float* b12 = (const float*)d_in[2];
    const float* W3  = (const float*)d_in[3];
    const float* b3  = (const float*)d_in[4];
    float* out = (float*)d_out;

    prep_kernel<<<BB * NN / PR, 512>>>(x, W12, b12, W3);
    main_kernel<<<dim3(BB * NN, MSPLIT), 256>>>(b3, out);
}